// round 13
// baseline (speedup 1.0000x reference)
#include <cuda_runtime.h>
#include <cstdint>

#define NB 32
#define NL 8192
#define NC 32
#define NF 32
#define TL 8                  // positions per CTA (= warps per CTA)
#define ROWS (TL + 3)         // halo: 2 before, 1 after
#define PAD 36                // 16B-aligned batch rows -> LDS.128 x loads
#define NSTG 3                // pipeline stages (per-position ring), taps 0-3 only
#define CCH 2                 // channels per chunk
#define NCHUNK (NC / CCH)     // 16 chunks
#define NTAPR 4               // taps in the TMA ring (tap 4 goes via LDG)
#define TAPCH_BYTES (CCH * NF * 4)        // 256 B per (tap,pos) chunk
#define POS_BYTES (NTAPR * TAPCH_BYTES)   // 1024 B per pos per stage
#define STG_BYTES (TL * POS_BYTES)        // 8192 B per stage
#define MBAR_OFF 0                        // 8 pos * 48 B = 384
#define WS_OFF 512
#define SX_OFF (WS_OFF + NSTG * STG_BYTES)    // 512 + 24576 = 25088
#define SX_BYTES (ROWS * NC * PAD * 4)        // 50688
#define SMEM_TOTAL (SX_OFF + SX_BYTES)        // 75776 -> 3 CTAs/SM

// Inter-layer scratch for h = leaky(bn(lc1(x)))
__device__ float g_h[(size_t)NB * NL * NC];

typedef unsigned long long ull;

__device__ __forceinline__ ull dup2(float w) {
    ull r; unsigned int u = __float_as_uint(w);
    asm("mov.b64 %0, {%1, %1};" : "=l"(r) : "r"(u));
    return r;
}
__device__ __forceinline__ void fma2(ull& d, ull a, ull b) {
    asm("fma.rn.f32x2 %0, %1, %2, %0;" : "+l"(d) : "l"(a), "l"(b));
}
__device__ __forceinline__ float2 unpk(ull v) {
    float2 f;
    asm("mov.b64 {%0, %1}, %2;" : "=f"(f.x), "=f"(f.y) : "l"(v));
    return f;
}
__device__ __forceinline__ float lky(float v) { return v >= 0.f ? v : 0.3f * v; }

__device__ __forceinline__ uint32_t s2u(const void* p) {
    uint32_t a;
    asm("{ .reg .u64 t; cvta.to.shared.u64 t, %1; cvt.u32.u64 %0, t; }" : "=r"(a) : "l"(p));
    return a;
}
__device__ __forceinline__ void mbar_init(uint32_t a, uint32_t c) {
    asm volatile("mbarrier.init.shared.b64 [%0], %1;" :: "r"(a), "r"(c) : "memory");
}
__device__ __forceinline__ void mbar_arrive(uint32_t a) {
    asm volatile("mbarrier.arrive.shared.b64 _, [%0];" :: "r"(a) : "memory");
}
__device__ __forceinline__ void mbar_expect(uint32_t a, uint32_t tx) {
    asm volatile("mbarrier.arrive.expect_tx.shared.b64 _, [%0], %1;" :: "r"(a), "r"(tx) : "memory");
}
__device__ __forceinline__ void mbar_wait(uint32_t a, uint32_t ph) {
    asm volatile(
        "{\n\t.reg .pred P;\n"
        "W%=:\n\tmbarrier.try_wait.parity.shared.b64 P, [%0], %1, 0x989680;\n\t"
        "@P bra D%=;\n\tbra W%=;\nD%=:\n\t}"
        :: "r"(a), "r"(ph) : "memory");
}
__device__ __forceinline__ void bulk_cp(uint32_t dst, const float* src, uint32_t bytes, uint32_t mbar) {
    asm volatile("cp.async.bulk.shared::cta.global.mbarrier::complete_tx::bytes [%0], [%1], %2, [%3];"
                 :: "r"(dst), "l"(src), "r"(bytes), "r"(mbar) : "memory");
}

// 16-fma2 update: 4 batch-pairs (2x LDS.128) times 4 dup'd weights
__device__ __forceinline__ void tap_fma(ull acc[4][4], const float* xr,
                                        ull d0, ull d1, ull d2, ull d3) {
    ulonglong2 xa = *reinterpret_cast<const ulonglong2*>(xr);
    ulonglong2 xb = *reinterpret_cast<const ulonglong2*>(xr + 4);
    fma2(acc[0][0], xa.x, d0); fma2(acc[0][1], xa.x, d1);
    fma2(acc[0][2], xa.x, d2); fma2(acc[0][3], xa.x, d3);
    fma2(acc[1][0], xa.y, d0); fma2(acc[1][1], xa.y, d1);
    fma2(acc[1][2], xa.y, d2); fma2(acc[1][3], xa.y, d3);
    fma2(acc[2][0], xb.x, d0); fma2(acc[2][1], xb.x, d1);
    fma2(acc[2][2], xb.x, d2); fma2(acc[2][3], xb.x, d3);
    fma2(acc[3][0], xb.y, d0); fma2(acc[3][1], xb.y, d1);
    fma2(acc[3][2], xb.y, d2); fma2(acc[3][3], xb.y, d3);
}

template <bool SECOND>
__global__ void __launch_bounds__(256, 3)
lc_kernel(const float* __restrict__ in,
          const float* __restrict__ wts,     // [K, L, C, F]
          const float* __restrict__ bias,    // [L, F]
          const float* __restrict__ gamma,
          const float* __restrict__ beta,
          const float* __restrict__ mean,
          const float* __restrict__ var,
          const float* __restrict__ residx,  // original x (L2 only)
          float* __restrict__ out)
{
    extern __shared__ char smem[];
    const uint32_t sbase = s2u(smem);
    float* sx = reinterpret_cast<float*>(smem + SX_OFF);

    const int tid  = threadIdx.x;
    const int warp = tid >> 5;
    const int lane = tid & 31;
    const int l0   = blockIdx.x * TL;
    const int l    = l0 + warp;                 // one warp = one position

    // Per-position rings (3 stages): full[s] at pos*48+s*16, empty at +8
    if (tid < TL * NSTG) {
        int p = tid / NSTG, s = tid % NSTG;
        mbar_init(sbase + MBAR_OFF + p * 48 + s * 16, 1);       // full: expect_tx
        mbar_init(sbase + MBAR_OFF + p * 48 + s * 16 + 8, 1);   // empty: own warp
    }
    __syncthreads();

    const uint32_t mb = sbase + MBAR_OFF + warp * 48;
    const size_t tapStride = (size_t)NL * NC * NF;
    const float* wl = wts + (size_t)l * NC * NF;
    const uint32_t wposdst = sbase + WS_OFF + warp * POS_BYTES;

    const int f0 = (lane & 7) << 2;             // 4 filters / thread
    const int b0 = (lane >> 3) << 3;            // 8 batches / thread

    // Tap-4 weight stream (LDG, register-prefetched one chunk ahead)
    const float* weL = wts + 4 * tapStride + (size_t)l * NC * NF + f0;
    float4 eA0 = __ldcs((const float4*)(weL + 0));           // chunk 0, cc 0/1
    float4 eA1 = __ldcs((const float4*)(weL + 32));
    float4 eB0 = __ldcs((const float4*)(weL + 64));          // chunk 1
    float4 eB1 = __ldcs((const float4*)(weL + 96));

    int pslot = 0, pph = 1;   // producer cursor (fresh empty-waits pass)
    #pragma unroll
    for (int s = 0; s < NSTG - 1; ++s) {       // prologue: 2 chunks in flight
        mbar_wait(mb + pslot * 16 + 8, (uint32_t)pph);
        if (lane == 0) {
            mbar_expect(mb + pslot * 16, POS_BYTES);
            #pragma unroll
            for (int k = 0; k < NTAPR; ++k)
                bulk_cp(wposdst + pslot * STG_BYTES + k * TAPCH_BYTES,
                        wl + (size_t)k * tapStride + s * (CCH * NF),
                        TAPCH_BYTES, mb + pslot * 16);
        }
        if (++pslot == NSTG) { pslot = 0; pph ^= 1; }
    }

    // Stage input tile [lp][c][b] while weight DMA is in flight
    const float* src = SECOND ? (const float*)g_h : in;
    for (int idx = tid; idx < NB * ROWS * NC; idx += 256) {
        int b   = idx / (ROWS * NC);
        int rem = idx - b * (ROWS * NC);
        int lp  = rem >> 5;
        int c   = rem & 31;
        int gl  = (l0 + lp - 2) & (NL - 1);
        sx[(lp * NC + c) * PAD + b] = src[((size_t)b * NL + gl) * NC + c];
    }
    __syncthreads();

    ull acc[4][4];
    #pragma unroll
    for (int i = 0; i < 4; ++i)
        #pragma unroll
        for (int j = 0; j < 4; ++j) acc[i][j] = 0ull;

    // Single x base; tap-row offsets are compile-time immediates
    const float* xrB = sx + warp * (NC * PAD) + b0;
    const char*  wsb = smem + WS_OFF + warp * POS_BYTES + f0 * 4;

    auto consume = [&](int slot, int chunk, const float4& e0, const float4& e1) {
        const char* wp0 = wsb + slot * STG_BYTES;
        #pragma unroll
        for (int cc = 0; cc < CCH; ++cc) {
            const int c = chunk * CCH + cc;
            const float4 wA = *reinterpret_cast<const float4*>(wp0 + 0 * TAPCH_BYTES + cc * 128);
            const float4 wB = *reinterpret_cast<const float4*>(wp0 + 1 * TAPCH_BYTES + cc * 128);
            const float4 wC = *reinterpret_cast<const float4*>(wp0 + 2 * TAPCH_BYTES + cc * 128);
            const float4 wD = *reinterpret_cast<const float4*>(wp0 + 3 * TAPCH_BYTES + cc * 128);
            const float4& wE = cc ? e1 : e0;
            tap_fma(acc, xrB + 2 * NC * PAD + c * PAD,
                    dup2(wA.x + wB.x), dup2(wA.y + wB.y),
                    dup2(wA.z + wB.z), dup2(wA.w + wB.w));
            tap_fma(acc, xrB + 1 * NC * PAD + c * PAD, dup2(wC.x), dup2(wC.y), dup2(wC.z), dup2(wC.w));
            tap_fma(acc, xrB + 3 * NC * PAD + c * PAD, dup2(wD.x), dup2(wD.y), dup2(wD.z), dup2(wD.w));
            tap_fma(acc, xrB + 0 * NC * PAD + c * PAD, dup2(wE.x), dup2(wE.y), dup2(wE.z), dup2(wE.w));
        }
    };
    auto produce = [&](int slot, int chunk) {   // TMA-fetch taps 0-3 of `chunk`
        if (lane == 0) {
            mbar_expect(mb + slot * 16, POS_BYTES);
            #pragma unroll
            for (int k = 0; k < NTAPR; ++k)
                bulk_cp(wposdst + slot * STG_BYTES + k * TAPCH_BYTES,
                        wl + (size_t)k * tapStride + chunk * (CCH * NF),
                        TAPCH_BYTES, mb + slot * 16);
        }
    };

    int cslot = 0, cph = 0;
    #pragma unroll 1
    for (int it = 0; it < NCHUNK / 2; ++it) {
        // even chunk 2it
        if (2 * it + 2 < NCHUNK) {
            mbar_wait(mb + pslot * 16 + 8, (uint32_t)pph);
            produce(pslot, 2 * it + 2);
            if (++pslot == NSTG) { pslot = 0; pph ^= 1; }
        }
        mbar_wait(mb + cslot * 16, (uint32_t)cph);
        consume(cslot, 2 * it, eA0, eA1);
        if (lane == 0) mbar_arrive(mb + cslot * 16 + 8);
        if (++cslot == NSTG) { cslot = 0; cph ^= 1; }
        {   // refill tap-4 regs for chunk 2it+2 (clamped dead-load at the tail)
            int ch = (2 * it + 2 < NCHUNK) ? (2 * it + 2) : (NCHUNK - 1);
            eA0 = __ldcs((const float4*)(weL + ch * 64));
            eA1 = __ldcs((const float4*)(weL + ch * 64 + 32));
        }

        // odd chunk 2it+1
        if (2 * it + 3 < NCHUNK) {
            mbar_wait(mb + pslot * 16 + 8, (uint32_t)pph);
            produce(pslot, 2 * it + 3);
            if (++pslot == NSTG) { pslot = 0; pph ^= 1; }
        }
        mbar_wait(mb + cslot * 16, (uint32_t)cph);
        consume(cslot, 2 * it + 1, eB0, eB1);
        if (lane == 0) mbar_arrive(mb + cslot * 16 + 8);
        if (++cslot == NSTG) { cslot = 0; cph ^= 1; }
        {   // refill tap-4 regs for chunk 2it+3
            int ch = (2 * it + 3 < NCHUNK) ? (2 * it + 3) : (NCHUNK - 1);
            eB0 = __ldcs((const float4*)(weL + ch * 64));
            eB1 = __ldcs((const float4*)(weL + ch * 64 + 32));
        }
    }

    // Epilogue: fold BN + the reference's double-added bias into scale/shift
    float4 ga = *reinterpret_cast<const float4*>(gamma + f0);
    float4 bt = *reinterpret_cast<const float4*>(beta + f0);
    float4 mn = *reinterpret_cast<const float4*>(mean + f0);
    float4 vr = *reinterpret_cast<const float4*>(var + f0);
    float4 bi = *reinterpret_cast<const float4*>(bias + (size_t)l * NF + f0);

    float scv[4], shv[4];
    scv[0] = ga.x * rsqrtf(vr.x + 1e-3f); shv[0] = bt.x + (2.f * bi.x - mn.x) * scv[0];
    scv[1] = ga.y * rsqrtf(vr.y + 1e-3f); shv[1] = bt.y + (2.f * bi.y - mn.y) * scv[1];
    scv[2] = ga.z * rsqrtf(vr.z + 1e-3f); shv[2] = bt.z + (2.f * bi.z - mn.z) * scv[2];
    scv[3] = ga.w * rsqrtf(vr.w + 1e-3f); shv[3] = bt.w + (2.f * bi.w - mn.w) * scv[3];

    float* dstbase = SECOND ? out : (float*)g_h;

    #pragma unroll
    for (int bp = 0; bp < 4; ++bp) {
        float2 v[4];
        #pragma unroll
        for (int ff = 0; ff < 4; ++ff) v[ff] = unpk(acc[bp][ff]);

        const int bl = b0 + 2 * bp;
        float o0[4], o1[4];
        #pragma unroll
        for (int ff = 0; ff < 4; ++ff) {
            o0[ff] = v[ff].x * scv[ff] + shv[ff];
            o1[ff] = v[ff].y * scv[ff] + shv[ff];
        }
        if (SECOND) {
            float4 r0 = *reinterpret_cast<const float4*>(residx + ((size_t)bl * NL + l) * NC + f0);
            float4 r1 = *reinterpret_cast<const float4*>(residx + ((size_t)(bl + 1) * NL + l) * NC + f0);
            o0[0] += r0.x; o0[1] += r0.y; o0[2] += r0.z; o0[3] += r0.w;
            o1[0] += r1.x; o1[1] += r1.y; o1[2] += r1.z; o1[3] += r1.w;
        }
        #pragma unroll
        for (int ff = 0; ff < 4; ++ff) { o0[ff] = lky(o0[ff]); o1[ff] = lky(o1[ff]); }

        float* d0 = dstbase + ((size_t)bl * NL + l) * NC + f0;
        float* d1 = dstbase + ((size_t)(bl + 1) * NL + l) * NC + f0;
        *reinterpret_cast<float4*>(d0) = make_float4(o0[0], o0[1], o0[2], o0[3]);
        *reinterpret_cast<float4*>(d1) = make_float4(o1[0], o1[1], o1[2], o1[3]);
    }
}

extern "C" void kernel_launch(void* const* d_in, const int* in_sizes, int n_in,
                              void* d_out, int out_size) {
    (void)in_sizes; (void)n_in; (void)out_size;
    const float* x   = (const float*)d_in[0];
    const float* k1  = (const float*)d_in[1];
    const float* b1  = (const float*)d_in[2];
    const float* g1  = (const float*)d_in[3];
    const float* be1 = (const float*)d_in[4];
    const float* m1  = (const float*)d_in[5];
    const float* v1  = (const float*)d_in[6];
    const float* k2  = (const float*)d_in[7];
    const float* b2  = (const float*)d_in[8];
    const float* g2  = (const float*)d_in[9];
    const float* be2 = (const float*)d_in[10];
    const float* m2  = (const float*)d_in[11];
    const float* v2  = (const float*)d_in[12];
    float* out = (float*)d_out;

    cudaFuncSetAttribute(lc_kernel<false>, cudaFuncAttributeMaxDynamicSharedMemorySize, SMEM_TOTAL);
    cudaFuncSetAttribute(lc_kernel<true >, cudaFuncAttributeMaxDynamicSharedMemorySize, SMEM_TOTAL);

    dim3 grid(NL / TL);
    lc_kernel<false><<<grid, 256, SMEM_TOTAL>>>(x, k1, b1, g1, be1, m1, v1, nullptr, nullptr);
    lc_kernel<true ><<<grid, 256, SMEM_TOTAL>>>(nullptr, k2, b2, g2, be2, m2, v2, x, out);
}

// round 14
// speedup vs baseline: 1.8668x; 1.8668x over previous
#include <cuda_runtime.h>
#include <cstdint>

#define NB 32
#define NL 8192
#define NC 32
#define NF 32
#define TL 8                  // positions per CTA (= warps per CTA)
#define ROWS (TL + 3)         // halo: 2 before, 1 after
#define PAD 36                // 16B-aligned batch rows -> LDS.128 x loads
#define NSTG 2                // pipeline stages (per-position ring)
#define CCH 2                 // channels per chunk
#define NCHUNK (NC / CCH)     // 16 chunks
#define TAPCH_BYTES (CCH * NF * 4)        // 256 B per (tap,pos) chunk
#define POS_BYTES (5 * TAPCH_BYTES)       // 1280 B per pos per stage
#define STG_BYTES (TL * POS_BYTES)        // 10240 B per stage
#define MBAR_OFF 0                        // 8 pos * 32 B (2 full barriers each)
#define WS_OFF 512
#define SX_OFF (WS_OFF + NSTG * STG_BYTES)    // 512 + 20480 = 20992
#define SX_BYTES (ROWS * NC * PAD * 4)        // 50688
#define SMEM_TOTAL (SX_OFF + SX_BYTES)        // 71680 -> 3 CTAs/SM

// Inter-layer scratch for h = leaky(bn(lc1(x)))
__device__ float g_h[(size_t)NB * NL * NC];

typedef unsigned long long ull;

__device__ __forceinline__ ull dup2(float w) {
    ull r; unsigned int u = __float_as_uint(w);
    asm("mov.b64 %0, {%1, %1};" : "=l"(r) : "r"(u));
    return r;
}
__device__ __forceinline__ void fma2(ull& d, ull a, ull b) {
    asm("fma.rn.f32x2 %0, %1, %2, %0;" : "+l"(d) : "l"(a), "l"(b));
}
__device__ __forceinline__ float2 unpk(ull v) {
    float2 f;
    asm("mov.b64 {%0, %1}, %2;" : "=f"(f.x), "=f"(f.y) : "l"(v));
    return f;
}
__device__ __forceinline__ float lky(float v) { return v >= 0.f ? v : 0.3f * v; }

__device__ __forceinline__ uint32_t s2u(const void* p) {
    uint32_t a;
    asm("{ .reg .u64 t; cvta.to.shared.u64 t, %1; cvt.u32.u64 %0, t; }" : "=r"(a) : "l"(p));
    return a;
}
__device__ __forceinline__ void mbar_init(uint32_t a, uint32_t c) {
    asm volatile("mbarrier.init.shared.b64 [%0], %1;" :: "r"(a), "r"(c) : "memory");
}
__device__ __forceinline__ void mbar_expect(uint32_t a, uint32_t tx) {
    asm volatile("mbarrier.arrive.expect_tx.shared.b64 _, [%0], %1;" :: "r"(a), "r"(tx) : "memory");
}
// Non-blocking poll: predicate resolves ~150 cyc later, hidden under compute
__device__ __forceinline__ uint32_t mbar_poll(uint32_t a, uint32_t ph) {
    uint32_t r;
    asm volatile(
        "{\n\t.reg .pred P;\n\t"
        "mbarrier.test_wait.parity.shared.b64 P, [%1], %2;\n\t"
        "selp.b32 %0, 1, 0, P;\n\t}"
        : "=r"(r) : "r"(a), "r"(ph) : "memory");
    return r;
}
__device__ __forceinline__ void mbar_wait(uint32_t a, uint32_t ph) {
    asm volatile(
        "{\n\t.reg .pred P;\n"
        "W%=:\n\tmbarrier.try_wait.parity.shared.b64 P, [%0], %1, 0x989680;\n\t"
        "@P bra D%=;\n\tbra W%=;\nD%=:\n\t}"
        :: "r"(a), "r"(ph) : "memory");
}
__device__ __forceinline__ void bulk_cp(uint32_t dst, const float* src, uint32_t bytes, uint32_t mbar) {
    asm volatile("cp.async.bulk.shared::cta.global.mbarrier::complete_tx::bytes [%0], [%1], %2, [%3];"
                 :: "r"(dst), "l"(src), "r"(bytes), "r"(mbar) : "memory");
}

// 16-fma2 update: 4 batch-pairs (2x LDS.128) times 4 dup'd weights
__device__ __forceinline__ void tap_fma(ull acc[4][4], const float* xr,
                                        ull d0, ull d1, ull d2, ull d3) {
    ulonglong2 xa = *reinterpret_cast<const ulonglong2*>(xr);
    ulonglong2 xb = *reinterpret_cast<const ulonglong2*>(xr + 4);
    fma2(acc[0][0], xa.x, d0); fma2(acc[0][1], xa.x, d1);
    fma2(acc[0][2], xa.x, d2); fma2(acc[0][3], xa.x, d3);
    fma2(acc[1][0], xa.y, d0); fma2(acc[1][1], xa.y, d1);
    fma2(acc[1][2], xa.y, d2); fma2(acc[1][3], xa.y, d3);
    fma2(acc[2][0], xb.x, d0); fma2(acc[2][1], xb.x, d1);
    fma2(acc[2][2], xb.x, d2); fma2(acc[2][3], xb.x, d3);
    fma2(acc[3][0], xb.y, d0); fma2(acc[3][1], xb.y, d1);
    fma2(acc[3][2], xb.y, d2); fma2(acc[3][3], xb.y, d3);
}

template <bool SECOND>
__global__ void __launch_bounds__(256, 3)
lc_kernel(const float* __restrict__ in,
          const float* __restrict__ wts,     // [K, L, C, F]
          const float* __restrict__ bias,    // [L, F]
          const float* __restrict__ gamma,
          const float* __restrict__ beta,
          const float* __restrict__ mean,
          const float* __restrict__ var,
          const float* __restrict__ residx,  // original x (L2 only)
          float* __restrict__ out)
{
    extern __shared__ char smem[];
    const uint32_t sbase = s2u(smem);
    float* sx = reinterpret_cast<float*>(smem + SX_OFF);

    const int tid  = threadIdx.x;
    const int warp = tid >> 5;
    const int lane = tid & 31;
    const int l0   = blockIdx.x * TL;
    const int l    = l0 + warp;                 // one warp = one position

    // 2 full barriers per position (no empty barriers: same-warp ring,
    // program order makes slot reuse safe)
    if (tid < TL * NSTG) {
        int p = tid >> 1, s = tid & 1;
        mbar_init(sbase + MBAR_OFF + p * 32 + s * 16, 1);
    }
    __syncthreads();

    const uint32_t mb = sbase + MBAR_OFF + warp * 32;
    const size_t tapStride = (size_t)NL * NC * NF;
    const float* wl = wts + (size_t)l * NC * NF;
    const uint32_t wposdst = sbase + WS_OFF + warp * POS_BYTES;

    auto produce = [&](int slot, int chunk) {   // fetch `chunk` into `slot`
        if (lane == 0) {
            mbar_expect(mb + slot * 16, POS_BYTES);
            #pragma unroll
            for (int k = 0; k < 5; ++k)
                bulk_cp(wposdst + slot * STG_BYTES + k * TAPCH_BYTES,
                        wl + (size_t)k * tapStride + chunk * (CCH * NF),
                        TAPCH_BYTES, mb + slot * 16);
        }
    };

    // Prologue: both slots in flight immediately
    produce(0, 0);
    produce(1, 1);

    // Stage input tile [lp][c][b] while weight DMA is in flight
    const float* src = SECOND ? (const float*)g_h : in;
    for (int idx = tid; idx < NB * ROWS * NC; idx += 256) {
        int b   = idx / (ROWS * NC);
        int rem = idx - b * (ROWS * NC);
        int lp  = rem >> 5;
        int c   = rem & 31;
        int gl  = (l0 + lp - 2) & (NL - 1);
        sx[(lp * NC + c) * PAD + b] = src[((size_t)b * NL + gl) * NC + c];
    }
    __syncthreads();

    const int f0 = (lane & 7) << 2;             // 4 filters / thread
    const int b0 = (lane >> 3) << 3;            // 8 batches / thread

    ull acc[4][4];
    #pragma unroll
    for (int i = 0; i < 4; ++i)
        #pragma unroll
        for (int j = 0; j < 4; ++j) acc[i][j] = 0ull;

    const float* xrB = sx + warp * (NC * PAD) + b0;
    const char*  wsb = smem + WS_OFF + warp * POS_BYTES + f0 * 4;

    auto consume = [&](int slot, int chunk) {
        const char* wp0 = wsb + slot * STG_BYTES;
        #pragma unroll
        for (int cc = 0; cc < CCH; ++cc) {
            const int c = chunk * CCH + cc;
            const float4 wA = *reinterpret_cast<const float4*>(wp0 + 0 * TAPCH_BYTES + cc * 128);
            const float4 wB = *reinterpret_cast<const float4*>(wp0 + 1 * TAPCH_BYTES + cc * 128);
            const float4 wC = *reinterpret_cast<const float4*>(wp0 + 2 * TAPCH_BYTES + cc * 128);
            const float4 wD = *reinterpret_cast<const float4*>(wp0 + 3 * TAPCH_BYTES + cc * 128);
            const float4 wE = *reinterpret_cast<const float4*>(wp0 + 4 * TAPCH_BYTES + cc * 128);
            tap_fma(acc, xrB + 2 * NC * PAD + c * PAD,
                    dup2(wA.x + wB.x), dup2(wA.y + wB.y),
                    dup2(wA.z + wB.z), dup2(wA.w + wB.w));
            tap_fma(acc, xrB + 1 * NC * PAD + c * PAD, dup2(wC.x), dup2(wC.y), dup2(wC.z), dup2(wC.w));
            tap_fma(acc, xrB + 3 * NC * PAD + c * PAD, dup2(wD.x), dup2(wD.y), dup2(wD.z), dup2(wD.w));
            tap_fma(acc, xrB + 0 * NC * PAD + c * PAD, dup2(wE.x), dup2(wE.y), dup2(wE.z), dup2(wE.w));
        }
    };

    // Wait for chunk 0 (slot 0, phase 0)
    mbar_wait(mb, 0u);

    // Steady state, unrolled by 2: slots/phases are immediates.
    // it = 0..6 full; iteration tail (it=7) peeled below.
    #pragma unroll 1
    for (int it = 0; it < NCHUNK / 2 - 1; ++it) {
        const uint32_t ph = (uint32_t)(it & 1);

        // even chunk 2it (slot 0, phase ph); poll chunk 2it+1 (slot 1, ph) early
        uint32_t rdy = mbar_poll(mb + 16, ph);
        consume(0, 2 * it);
        produce(0, 2 * it + 2);                 // safe: after consume(0,·) in program order
        if (!rdy) mbar_wait(mb + 16, ph);

        // odd chunk 2it+1 (slot 1, phase ph); poll chunk 2it+2 (slot 0, ph^1) early
        uint32_t rdy2 = mbar_poll(mb, ph ^ 1u);
        consume(1, 2 * it + 1);
        produce(1, 2 * it + 3);
        if (!rdy2) mbar_wait(mb, ph ^ 1u);
    }
    {   // tail: chunks 14 (slot 0, phase 1) and 15 (slot 1, phase 1)
        uint32_t rdy = mbar_poll(mb + 16, 1u);
        consume(0, NCHUNK - 2);
        if (!rdy) mbar_wait(mb + 16, 1u);
        consume(1, NCHUNK - 1);
    }

    // Epilogue: fold BN + the reference's double-added bias into scale/shift
    float4 ga = *reinterpret_cast<const float4*>(gamma + f0);
    float4 bt = *reinterpret_cast<const float4*>(beta + f0);
    float4 mn = *reinterpret_cast<const float4*>(mean + f0);
    float4 vr = *reinterpret_cast<const float4*>(var + f0);
    float4 bi = *reinterpret_cast<const float4*>(bias + (size_t)l * NF + f0);

    float scv[4], shv[4];
    scv[0] = ga.x * rsqrtf(vr.x + 1e-3f); shv[0] = bt.x + (2.f * bi.x - mn.x) * scv[0];
    scv[1] = ga.y * rsqrtf(vr.y + 1e-3f); shv[1] = bt.y + (2.f * bi.y - mn.y) * scv[1];
    scv[2] = ga.z * rsqrtf(vr.z + 1e-3f); shv[2] = bt.z + (2.f * bi.z - mn.z) * scv[2];
    scv[3] = ga.w * rsqrtf(vr.w + 1e-3f); shv[3] = bt.w + (2.f * bi.w - mn.w) * scv[3];

    float* dstbase = SECOND ? out : (float*)g_h;

    #pragma unroll
    for (int bp = 0; bp < 4; ++bp) {
        float2 v[4];
        #pragma unroll
        for (int ff = 0; ff < 4; ++ff) v[ff] = unpk(acc[bp][ff]);

        const int bl = b0 + 2 * bp;
        float o0[4], o1[4];
        #pragma unroll
        for (int ff = 0; ff < 4; ++ff) {
            o0[ff] = v[ff].x * scv[ff] + shv[ff];
            o1[ff] = v[ff].y * scv[ff] + shv[ff];
        }
        if (SECOND) {
            float4 r0 = *reinterpret_cast<const float4*>(residx + ((size_t)bl * NL + l) * NC + f0);
            float4 r1 = *reinterpret_cast<const float4*>(residx + ((size_t)(bl + 1) * NL + l) * NC + f0);
            o0[0] += r0.x; o0[1] += r0.y; o0[2] += r0.z; o0[3] += r0.w;
            o1[0] += r1.x; o1[1] += r1.y; o1[2] += r1.z; o1[3] += r1.w;
        }
        #pragma unroll
        for (int ff = 0; ff < 4; ++ff) { o0[ff] = lky(o0[ff]); o1[ff] = lky(o1[ff]); }

        float* d0 = dstbase + ((size_t)bl * NL + l) * NC + f0;
        float* d1 = dstbase + ((size_t)(bl + 1) * NL + l) * NC + f0;
        *reinterpret_cast<float4*>(d0) = make_float4(o0[0], o0[1], o0[2], o0[3]);
        *reinterpret_cast<float4*>(d1) = make_float4(o1[0], o1[1], o1[2], o1[3]);
    }
}

extern "C" void kernel_launch(void* const* d_in, const int* in_sizes, int n_in,
                              void* d_out, int out_size) {
    (void)in_sizes; (void)n_in; (void)out_size;
    const float* x   = (const float*)d_in[0];
    const float* k1  = (const float*)d_in[1];
    const float* b1  = (const float*)d_in[2];
    const float* g1  = (const float*)d_in[3];
    const float* be1 = (const float*)d_in[4];
    const float* m1  = (const float*)d_in[5];
    const float* v1  = (const float*)d_in[6];
    const float* k2  = (const float*)d_in[7];
    const float* b2  = (const float*)d_in[8];
    const float* g2  = (const float*)d_in[9];
    const float* be2 = (const float*)d_in[10];
    const float* m2  = (const float*)d_in[11];
    const float* v2  = (const float*)d_in[12];
    float* out = (float*)d_out;

    cudaFuncSetAttribute(lc_kernel<false>, cudaFuncAttributeMaxDynamicSharedMemorySize, SMEM_TOTAL);
    cudaFuncSetAttribute(lc_kernel<true >, cudaFuncAttributeMaxDynamicSharedMemorySize, SMEM_TOTAL);

    dim3 grid(NL / TL);
    lc_kernel<false><<<grid, 256, SMEM_TOTAL>>>(x, k1, b1, g1, be1, m1, v1, nullptr, nullptr);
    lc_kernel<true ><<<grid, 256, SMEM_TOTAL>>>(nullptr, k2, b2, g2, be2, m2, v2, x, out);
}